// round 9
// baseline (speedup 1.0000x reference)
#include <cuda_runtime.h>
#include <math.h>
#include <cstdint>

#define BB 4
#define QQ 256
#define CCN 1024
#define QDIM 512
#define CDIM 512
#define HH 128

// ---------------- scratch (device globals; no allocation) ----------------
__device__ float g_Ec[BB * CCN * HH];        // e^{2*mc}  (B,C,H)
__device__ float g_Eq[BB * QQ * HH];         // e^{2*mq}  (B,Q,H)
__device__ float g_qpart[BB * QQ * QDIM];    // query @ lo_w[:,512:].T + lo_b
__device__ float g_wc[BB * QQ * CDIM];       // attn @ context
__device__ float g_attn_scratch[BB * QQ * CCN];

#define TWO_LOG2E 2.8853900817779268f

__device__ __forceinline__ float fast_ex2(float x) {
    float e; asm("ex2.approx.f32 %0, %1;" : "=f"(e) : "f"(x)); return e;
}
__device__ __forceinline__ float fast_rcp(float x) {
    float r; asm("rcp.approx.f32 %0, %1;" : "=f"(r) : "f"(x)); return r;
}
__device__ __forceinline__ float fast_tanh(float x) {
    float e = fast_ex2(x * TWO_LOG2E);
    return fmaf(-2.0f, fast_rcp(e + 1.0f), 1.0f);
}

// ---------------- packed f32x2 helpers ----------------
__device__ __forceinline__ void fma2(unsigned long long& acc,
                                     unsigned long long a2,
                                     unsigned long long b2) {
    asm("fma.rn.f32x2 %0, %1, %2, %0;" : "+l"(acc) : "l"(a2), "l"(b2));
}
__device__ __forceinline__ unsigned long long dup2(float a) {
    unsigned long long p;
    asm("mov.b64 %0, {%1, %1};" : "=l"(p) : "r"(__float_as_uint(a)));
    return p;
}
__device__ __forceinline__ void unpack2(unsigned long long p, float& lo, float& hi) {
    uint32_t l, h;
    asm("mov.b64 {%0, %1}, %2;" : "=r"(l), "=r"(h) : "l"(p));
    lo = __uint_as_float(l); hi = __uint_as_float(h);
}

// ---------------- 64x64 tile GEMM, 256 threads, 4-way split-K, 8x8/thread ---
// A: [M,K] row-major (lda). TRANSB: B is [N,K] (ldb); else [K,N] (ldb).
// 4 groups of 64 threads; group g covers k in [g*K/4,(g+1)*K/4), k-tile 8,
// double-buffered. acc held as 4 m-pairs x 8 n in packed f32x2.
// Requires K % 32 == 0. epi: 0 none, 1 ex2(2log2e*v), 2 tanh.
template <bool TRANSB>
__device__ __forceinline__
void gemm_sk8(const float* __restrict__ A, int lda,
              const float* __restrict__ Bm, int ldb,
              const float* __restrict__ bias,      // nullable
              const float* __restrict__ Add,       // nullable, ldc layout
              float* __restrict__ C, int ldc,
              int K, int m0, int n0, int epi)
{
    __shared__ __align__(16) float sp[8192];   // 32KB; aliased for reduction

    const int tid = threadIdx.x;
    const int g   = tid >> 6;        // k-group 0..3
    const int t   = tid & 63;        // thread in group
    const int ty  = t >> 3;          // 0..7 m octet
    const int tx  = t & 7;           // 0..7 n octet

    // per-group staging: As[buf][8][64] at +0, Bs[buf][8][64] at +1024 floats
    float* const Gp = sp + g * 2048;

    const int kq   = K >> 2;
    const int kbeg = g * kq;
    const int kend = kbeg + kq;

    unsigned long long acc2[4][8];   // m-pair p (rows 2p,2p+1), n column j
#pragma unroll
    for (int p = 0; p < 4; p++)
#pragma unroll
        for (int j = 0; j < 8; j++) acc2[p][j] = 0ull;

    // staging loader indices (2 float4 per thread per tile)
    const int r0  = t >> 1;          // 0..31 (rows lin 0..63 over 2 its)
    const int c4  = (t & 1) * 4;     // k sub {0,4}

    float4 avr[2], bvr[2];

    // ---- load tile (kk) into regs ----
    auto ldA = [&](int kk) {
#pragma unroll
        for (int it = 0; it < 2; it++)
            avr[it] = *(const float4*)&A[(long)(m0 + r0 + it * 32) * lda + kk + c4];
    };
    auto ldB = [&](int kk) {
        if (TRANSB) {
#pragma unroll
            for (int it = 0; it < 2; it++)
                bvr[it] = *(const float4*)&Bm[(long)(n0 + r0 + it * 32) * ldb + kk + c4];
        } else {
#pragma unroll
            for (int it = 0; it < 2; it++) {
                const int lin = t + 64 * it;         // 0..127
                bvr[it] = *(const float4*)&Bm[(long)(kk + (lin >> 4)) * ldb + n0 + (lin & 15) * 4];
            }
        }
    };
    // ---- store regs into staging buffer c ----
    auto stA = [&](int c) {
        float* As = Gp + c * 512;
#pragma unroll
        for (int it = 0; it < 2; it++) {
            const int row = r0 + it * 32;
            As[(c4 + 0) * 64 + row] = avr[it].x;
            As[(c4 + 1) * 64 + row] = avr[it].y;
            As[(c4 + 2) * 64 + row] = avr[it].z;
            As[(c4 + 3) * 64 + row] = avr[it].w;
        }
    };
    auto stB = [&](int c) {
        float* Bs = Gp + 1024 + c * 512;
        if (TRANSB) {
#pragma unroll
            for (int it = 0; it < 2; it++) {
                const int row = r0 + it * 32;
                Bs[(c4 + 0) * 64 + row] = bvr[it].x;
                Bs[(c4 + 1) * 64 + row] = bvr[it].y;
                Bs[(c4 + 2) * 64 + row] = bvr[it].z;
                Bs[(c4 + 3) * 64 + row] = bvr[it].w;
            }
        } else {
#pragma unroll
            for (int it = 0; it < 2; it++) {
                const int lin = t + 64 * it;
                *(float4*)&Bs[(lin >> 4) * 64 + (lin & 15) * 4] = bvr[it];
            }
        }
    };

    ldA(kbeg); ldB(kbeg);
    stA(0); stB(0);
    __syncthreads();

    int cur = 0;
    for (int kk = kbeg; kk < kend; kk += 8) {
        const bool more = (kk + 8) < kend;       // uniform across groups
        if (more) { ldA(kk + 8); ldB(kk + 8); }

        const float* As = Gp + cur * 512;
        const float* Bs = Gp + 1024 + cur * 512;
#pragma unroll
        for (int k = 0; k < 8; k++) {
            // a: 4 packed m-pairs (16B loads, m-contiguous)
            ulonglong2 ap0 = *(const ulonglong2*)&As[k * 64 + ty * 8];
            ulonglong2 ap1 = *(const ulonglong2*)&As[k * 64 + ty * 8 + 4];
            // b: 8 scalars -> dup2
            float4 b0 = *(const float4*)&Bs[k * 64 + tx * 8];
            float4 b1 = *(const float4*)&Bs[k * 64 + tx * 8 + 4];
            unsigned long long bd[8] = {
                dup2(b0.x), dup2(b0.y), dup2(b0.z), dup2(b0.w),
                dup2(b1.x), dup2(b1.y), dup2(b1.z), dup2(b1.w)
            };
            unsigned long long ap[4] = { ap0.x, ap0.y, ap1.x, ap1.y };
#pragma unroll
            for (int p = 0; p < 4; p++)
#pragma unroll
                for (int j = 0; j < 8; j++) fma2(acc2[p][j], ap[p], bd[j]);
        }

        if (more) { stA(cur ^ 1); stB(cur ^ 1); }
        __syncthreads();
        cur ^= 1;
    }

    // unpack to scalar grid f[8 rows][8 cols]
    float f[8][8];
#pragma unroll
    for (int p = 0; p < 4; p++)
#pragma unroll
        for (int j = 0; j < 8; j++) unpack2(acc2[p][j], f[2 * p][j], f[2 * p + 1][j]);

    // ---- cross-group reduction through smem (aliases staging) ----
    float* const red = sp;           // two 4096-float slots
    const int base = (ty * 8) * 64 + tx * 8;

    auto write_acc = [&](float* dst) {
#pragma unroll
        for (int i = 0; i < 8; i++) {
            *(float4*)&dst[base + i * 64]     = make_float4(f[i][0], f[i][1], f[i][2], f[i][3]);
            *(float4*)&dst[base + i * 64 + 4] = make_float4(f[i][4], f[i][5], f[i][6], f[i][7]);
        }
    };
    auto add_from = [&](const float* src) {
#pragma unroll
        for (int i = 0; i < 8; i++) {
            float4 u = *(const float4*)&src[base + i * 64];
            float4 w = *(const float4*)&src[base + i * 64 + 4];
            f[i][0] += u.x; f[i][1] += u.y; f[i][2] += u.z; f[i][3] += u.w;
            f[i][4] += w.x; f[i][5] += w.y; f[i][6] += w.z; f[i][7] += w.w;
        }
    };

    if (g == 1) write_acc(red);
    if (g == 3) write_acc(red + 4096);
    __syncthreads();
    if (g == 0) add_from(red);
    if (g == 2) add_from(red + 4096);
    __syncthreads();
    if (g == 2) write_acc(red);
    __syncthreads();

    if (g == 0) {
        add_from(red);
        const int nb = n0 + tx * 8;
        float4 ba = bias ? *(const float4*)&bias[nb]     : make_float4(0.f, 0.f, 0.f, 0.f);
        float4 bb = bias ? *(const float4*)&bias[nb + 4] : make_float4(0.f, 0.f, 0.f, 0.f);
#pragma unroll
        for (int i = 0; i < 8; i++) {
            const int m = m0 + ty * 8 + i;
            float4 v0 = make_float4(f[i][0] + ba.x, f[i][1] + ba.y, f[i][2] + ba.z, f[i][3] + ba.w);
            float4 v1 = make_float4(f[i][4] + bb.x, f[i][5] + bb.y, f[i][6] + bb.z, f[i][7] + bb.w);
            if (Add) {
                float4 a0 = *(const float4*)&Add[(long)m * ldc + nb];
                float4 a1 = *(const float4*)&Add[(long)m * ldc + nb + 4];
                v0.x += a0.x; v0.y += a0.y; v0.z += a0.z; v0.w += a0.w;
                v1.x += a1.x; v1.y += a1.y; v1.z += a1.z; v1.w += a1.w;
            }
            if (epi == 1) {
                v0.x = fast_ex2(v0.x * TWO_LOG2E); v0.y = fast_ex2(v0.y * TWO_LOG2E);
                v0.z = fast_ex2(v0.z * TWO_LOG2E); v0.w = fast_ex2(v0.w * TWO_LOG2E);
                v1.x = fast_ex2(v1.x * TWO_LOG2E); v1.y = fast_ex2(v1.y * TWO_LOG2E);
                v1.z = fast_ex2(v1.z * TWO_LOG2E); v1.w = fast_ex2(v1.w * TWO_LOG2E);
            } else if (epi == 2) {
                v0.x = fast_tanh(v0.x); v0.y = fast_tanh(v0.y);
                v0.z = fast_tanh(v0.z); v0.w = fast_tanh(v0.w);
                v1.x = fast_tanh(v1.x); v1.y = fast_tanh(v1.y);
                v1.z = fast_tanh(v1.z); v1.w = fast_tanh(v1.w);
            }
            *(float4*)&C[(long)m * ldc + nb]     = v0;
            *(float4*)&C[(long)m * ldc + nb + 4] = v1;
        }
    }
}

// ---------------- fused input projections: Ec, Eq, qpart (288 CTAs) --------
__global__ __launch_bounds__(256)
void proj_fused_kernel(const float* __restrict__ context,
                       const float* __restrict__ query,
                       const float* __restrict__ wc_w, const float* __restrict__ wc_b,
                       const float* __restrict__ wq_w, const float* __restrict__ wq_b,
                       const float* __restrict__ lo_w, const float* __restrict__ lo_b,
                       float* __restrict__ Ec, float* __restrict__ Eq,
                       float* __restrict__ qpart)
{
    const int i = blockIdx.x;
    if (i < 128) {               // Ec: 64 m-tiles x 2 n-tiles
        const int m0 = (i >> 1) * 64, n0 = (i & 1) * 64;
        gemm_sk8<true>(context, CDIM, wc_w, CDIM, wc_b, nullptr, Ec, HH,
                       CDIM, m0, n0, 1);
    } else if (i < 160) {        // Eq: 16 x 2
        const int j = i - 128;
        const int m0 = (j >> 1) * 64, n0 = (j & 1) * 64;
        gemm_sk8<true>(query, QDIM, wq_w, QDIM, wq_b, nullptr, Eq, HH,
                       QDIM, m0, n0, 1);
    } else {                     // qpart: 16 x 8
        const int j = i - 160;
        const int m0 = (j >> 3) * 64, n0 = (j & 7) * 64;
        gemm_sk8<true>(query, QDIM, lo_w + CDIM, QDIM + CDIM, lo_b, nullptr,
                       qpart, QDIM, QDIM, m0, n0, 0);
    }
}

// ---------------- wc = attn @ context (128 CTAs) ---------------------------
__global__ __launch_bounds__(256)
void gemm_nn_kernel(const float* __restrict__ attn,
                    const float* __restrict__ context,
                    float* __restrict__ wc)
{
    const int b = blockIdx.z;
    gemm_sk8<false>(attn + (long)b * QQ * CCN, CCN,
                    context + (long)b * CCN * CDIM, CDIM,
                    nullptr, nullptr,
                    wc + (long)b * QQ * CDIM, CDIM,
                    CCN, blockIdx.y * 64, blockIdx.x * 64, 0);
}

// ---------------- out = tanh(wc @ lo_w[:,:512].T + qpart) (128 CTAs) -------
__global__ __launch_bounds__(256)
void gemm_out_kernel(const float* __restrict__ wc,
                     const float* __restrict__ lo_w,
                     const float* __restrict__ qpart,
                     float* __restrict__ out)
{
    gemm_sk8<true>(wc, CDIM, lo_w, QDIM + CDIM, nullptr, qpart,
                   out, QDIM, CDIM, blockIdx.y * 64, blockIdx.x * 64, 2);
}

// ---------------- emission + masked softmax (unchanged) ----------------
#define QT 4
#define CH 32
#define NCHUNK (CCN / CH)
#define ECPAD 132

__global__ __launch_bounds__(128)
void emission_softmax2(const float* __restrict__ Ec,
                       const float* __restrict__ Eq,
                       const int* __restrict__ mask,
                       const float* __restrict__ we_w,
                       const float* __restrict__ we_b,
                       float* __restrict__ attn)
{
    __shared__ float ecs[CH][ECPAD];
    __shared__ float eqs[QT][HH];
    __shared__ float wes[HH];
    __shared__ int ms[CH];

    const int b  = blockIdx.y;
    const int q0 = blockIdx.x * QT;
    const int tid = threadIdx.x;
    const int lane = tid & 31;
    const int q = tid >> 5;

    if (tid < HH) wes[tid] = we_w[tid];
    {
        const float4* src = (const float4*)&Eq[(long)(b * QQ + q0) * HH];
        float4* dst = (float4*)&eqs[0][0];
        for (int i = tid; i < QT * HH / 4; i += 128) dst[i] = src[i];
    }
    __syncthreads();

    float W = 0.f;
#pragma unroll
    for (int h = 0; h < HH; h += 4) {
        float4 w4 = *(const float4*)&wes[h];
        W += (w4.x + w4.y) + (w4.z + w4.w);
    }
    const float eb = we_b[0];

    float es_l[NCHUNK];

    for (int ch = 0; ch < NCHUNK; ch++) {
        __syncthreads();
        {
            const float4* src = (const float4*)&Ec[((long)b * CCN + ch * CH) * HH];
            for (int i = tid; i < CH * HH / 4; i += 128) {
                int r  = i >> 5;
                int c4 = (i & 31) * 4;
                *(float4*)&ecs[r][c4] = src[i];
            }
            if (tid < CH) ms[tid] = mask[b * CCN + ch * CH + tid];
        }
        __syncthreads();

        float s0 = 0.f, s1 = 0.f;
#pragma unroll
        for (int h = 0; h < HH; h += 8) {
            float4 e0 = *(const float4*)&ecs[lane][h];
            float4 g0 = *(const float4*)&eqs[q][h];
            float4 w0 = *(const float4*)&wes[h];
            float4 e1 = *(const float4*)&ecs[lane][h + 4];
            float4 g1 = *(const float4*)&eqs[q][h + 4];
            float4 w1 = *(const float4*)&wes[h + 4];
            s0 += w0.x * fast_rcp(fmaf(e0.x, g0.x, 1.f));
            s1 += w0.y * fast_rcp(fmaf(e0.y, g0.y, 1.f));
            s0 += w0.z * fast_rcp(fmaf(e0.z, g0.z, 1.f));
            s1 += w0.w * fast_rcp(fmaf(e0.w, g0.w, 1.f));
            s0 += w1.x * fast_rcp(fmaf(e1.x, g1.x, 1.f));
            s1 += w1.y * fast_rcp(fmaf(e1.y, g1.y, 1.f));
            s0 += w1.z * fast_rcp(fmaf(e1.z, g1.z, 1.f));
            s1 += w1.w * fast_rcp(fmaf(e1.w, g1.w, 1.f));
        }
        float s = s0 + s1;
        es_l[ch] = ms[lane] ? (fmaf(-2.f, s, W) + eb) : -INFINITY;
    }

    float lm = -INFINITY;
#pragma unroll
    for (int ch = 0; ch < NCHUNK; ch++) lm = fmaxf(lm, es_l[ch]);
#pragma unroll
    for (int off = 16; off >= 1; off >>= 1)
        lm = fmaxf(lm, __shfl_xor_sync(0xffffffffu, lm, off));
    const bool ok = (lm > -3.0e38f);

    float ls = 0.f;
#pragma unroll
    for (int ch = 0; ch < NCHUNK; ch++) {
        float e = ok ? __expf(es_l[ch] - lm) : 0.f;
        es_l[ch] = e;
        ls += e;
    }
#pragma unroll
    for (int off = 16; off >= 1; off >>= 1)
        ls += __shfl_xor_sync(0xffffffffu, ls, off);
    const float inv = (ls > 0.f) ? 1.f / ls : 0.f;

    float* arow = attn + (long)(b * QQ + q0 + q) * CCN;
#pragma unroll
    for (int ch = 0; ch < NCHUNK; ch++) arow[ch * CH + lane] = es_l[ch] * inv;
}

// ---------------- launcher ----------------
extern "C" void kernel_launch(void* const* d_in, const int* in_sizes, int n_in,
                              void* d_out, int out_size)
{
    const float* query   = (const float*)d_in[0];
    const float* context = (const float*)d_in[1];
    const int*   mask    = (const int*)d_in[2];
    const float* wq_w = (const float*)d_in[3];
    const float* wq_b = (const float*)d_in[4];
    const float* wc_w = (const float*)d_in[5];
    const float* wc_b = (const float*)d_in[6];
    const float* we_w = (const float*)d_in[7];
    const float* we_b = (const float*)d_in[8];
    const float* lo_w = (const float*)d_in[9];
    const float* lo_b = (const float*)d_in[10];

    float *Ec, *Eq, *qpart, *wc, *attn_s;
    cudaGetSymbolAddress((void**)&Ec, g_Ec);
    cudaGetSymbolAddress((void**)&Eq, g_Eq);
    cudaGetSymbolAddress((void**)&qpart, g_qpart);
    cudaGetSymbolAddress((void**)&wc, g_wc);
    cudaGetSymbolAddress((void**)&attn_s, g_attn_scratch);

    const int nOut  = BB * QQ * QDIM;
    const int nAttn = BB * QQ * CCN;
    float* outPtr  = nullptr;
    float* attnPtr = nullptr;
    if (out_size >= nOut + nAttn) {
        outPtr  = (float*)d_out;
        attnPtr = (float*)d_out + nOut;
    } else if (out_size == nAttn) {
        attnPtr = (float*)d_out;
    } else {
        outPtr = (float*)d_out;
    }
    if (!attnPtr) attnPtr = attn_s;

    // 1) all input-only projections in one launch: Ec, Eq, qpart (288 CTAs)
    proj_fused_kernel<<<288, 256>>>(context, query, wc_w, wc_b, wq_w, wq_b,
                                    lo_w, lo_b, Ec, Eq, qpart);

    // 2) emission + softmax -> attn (256 CTAs)
    emission_softmax2<<<dim3(QQ / QT, BB), 128>>>(Ec, Eq, mask, we_w, we_b, attnPtr);

    if (outPtr) {
        // 3) wc = attn @ context (128 CTAs)
        gemm_nn_kernel<<<dim3(CDIM / 64, QQ / 64, BB), 256>>>(attnPtr, context, wc);

        // 4) out = tanh(wc @ lo_w[:,:512].T + qpart) (128 CTAs)
        gemm_out_kernel<<<dim3(QDIM / 64, BB * QQ / 64), 256>>>(wc, lo_w, qpart, outPtr);
    }
}

// round 10
// speedup vs baseline: 1.5605x; 1.5605x over previous
#include <cuda_runtime.h>
#include <math.h>
#include <cstdint>

#define BB 4
#define QQ 256
#define CCN 1024
#define QDIM 512
#define CDIM 512
#define HH 128

// ---------------- scratch (device globals; no allocation) ----------------
__device__ float g_Ec[BB * CCN * HH];        // e^{2*mc}  (B,C,H)
__device__ float g_Eq[BB * QQ * HH];         // e^{2*mq}  (B,Q,H)
__device__ float g_qpart[BB * QQ * QDIM];    // query @ lo_w[:,512:].T + lo_b
__device__ float g_wc[BB * QQ * CDIM];       // attn @ context
__device__ float g_attn_scratch[BB * QQ * CCN];

#define TWO_LOG2E 2.8853900817779268f

__device__ __forceinline__ float fast_ex2(float x) {
    float e; asm("ex2.approx.f32 %0, %1;" : "=f"(e) : "f"(x)); return e;
}
__device__ __forceinline__ float fast_rcp(float x) {
    float r; asm("rcp.approx.f32 %0, %1;" : "=f"(r) : "f"(x)); return r;
}
__device__ __forceinline__ float fast_tanh(float x) {
    float e = fast_ex2(x * TWO_LOG2E);
    return fmaf(-2.0f, fast_rcp(e + 1.0f), 1.0f);
}

// ---------------- packed f32x2 helpers ----------------
__device__ __forceinline__ void fma2(unsigned long long& acc,
                                     unsigned long long a2,
                                     unsigned long long b2) {
    asm("fma.rn.f32x2 %0, %1, %2, %0;" : "+l"(acc) : "l"(a2), "l"(b2));
}
__device__ __forceinline__ unsigned long long dup2(float a) {
    unsigned long long p;
    asm("mov.b64 %0, {%1, %1};" : "=l"(p) : "r"(__float_as_uint(a)));
    return p;
}
__device__ __forceinline__ void unpack2(unsigned long long p, float& lo, float& hi) {
    uint32_t l, h;
    asm("mov.b64 {%0, %1}, %2;" : "=r"(l), "=r"(h) : "l"(p));
    lo = __uint_as_float(l); hi = __uint_as_float(h);
}

// ---------------- 32x64x16 GEMM core, 128 threads, 3-stage prefetch --------
// A: [M,K] row-major (lda). TRANSB: B is [N,K] (ldb); else [K,N] (ldb).
// Double-buffered smem + TWO-tile-deep register prefetch: the STS for tile
// n+1 uses registers whose LDG was issued at tile n-1 (a full tile of slack),
// taking global-load latency off the inter-barrier critical path.
// epi: 0 = none, 1 = ex2(2*log2e*v), 2 = fast_tanh(v)
template <bool TRANSB>
__device__ __forceinline__
void gemm32(const float* __restrict__ A, int lda,
            const float* __restrict__ Bm, int ldb,
            const float* __restrict__ bias,      // nullable
            const float* __restrict__ Add,       // nullable, ldc layout
            float* __restrict__ C, int ldc,
            int K, int m0, int n0, int epi)
{
    __shared__ float As[2][16][32];
    __shared__ float Bs[2][16][64];

    const int tid = threadIdx.x;
    const int tx  = tid & 15;        // n group (x4)
    const int tyr = tid >> 4;        // 0..7 m group (x4)

    const int ar  = tid >> 2;        // 0..31
    const int ac4 = (tid & 3) * 4;   // k sub
    const int br  = tid >> 4;        // 0..15 (k)  (!TRANSB)
    const int bc4 = (tid & 15) * 4;  // 0..60 (n)  (!TRANSB)

    unsigned long long acc2[4][2];
#pragma unroll
    for (int i = 0; i < 4; i++) { acc2[i][0] = 0ull; acc2[i][1] = 0ull; }

    float4 av1, b01, b11;    // tile n+1 (ready to store)
    float4 av2, b02, b12;    // tile n+2 (in flight)

    // load tile at k-offset kk into (a,b0,b1)
    #define LD_TILE(kk, a, b0, b1)                                              \
        do {                                                                    \
            (a) = *(const float4*)&A[(long)(m0 + ar) * lda + (kk) + ac4];       \
            if (TRANSB) {                                                       \
                (b0) = *(const float4*)&Bm[(long)(n0 + ar) * ldb + (kk) + ac4]; \
                (b1) = *(const float4*)&Bm[(long)(n0 + 32 + ar) * ldb + (kk) + ac4]; \
            } else {                                                            \
                (b0) = *(const float4*)&Bm[(long)((kk) + br) * ldb + n0 + bc4]; \
                (b1) = *(const float4*)&Bm[(long)((kk) + 8 + br) * ldb + n0 + bc4]; \
            }                                                                   \
        } while (0)

    // store (a,b0,b1) into smem buffer bf
    #define ST_TILE(bf, a, b0, b1)                                              \
        do {                                                                    \
            As[bf][ac4 + 0][ar] = (a).x; As[bf][ac4 + 1][ar] = (a).y;           \
            As[bf][ac4 + 2][ar] = (a).z; As[bf][ac4 + 3][ar] = (a).w;           \
            if (TRANSB) {                                                       \
                Bs[bf][ac4 + 0][ar] = (b0).x; Bs[bf][ac4 + 1][ar] = (b0).y;     \
                Bs[bf][ac4 + 2][ar] = (b0).z; Bs[bf][ac4 + 3][ar] = (b0).w;     \
                Bs[bf][ac4 + 0][32 + ar] = (b1).x; Bs[bf][ac4 + 1][32 + ar] = (b1).y; \
                Bs[bf][ac4 + 2][32 + ar] = (b1).z; Bs[bf][ac4 + 3][32 + ar] = (b1).w; \
            } else {                                                            \
                *(float4*)&Bs[bf][br][bc4] = (b0);                              \
                *(float4*)&Bs[bf][8 + br][bc4] = (b1);                          \
            }                                                                   \
        } while (0)

    // prologue: tile 0 -> smem[0]; tile 1 -> regs
    LD_TILE(0, av1, b01, b11);
    ST_TILE(0, av1, b01, b11);
    if (16 < K) LD_TILE(16, av1, b01, b11);
    __syncthreads();

    int cur = 0;
    for (int k0 = 0; k0 < K; k0 += 16) {
        // issue LDG for tile n+2 (two tiles of slack before its STS)
        if (k0 + 32 < K) LD_TILE(k0 + 32, av2, b02, b12);

#pragma unroll
        for (int k = 0; k < 16; k++) {
            float4 a = *(const float4*)&As[cur][k][tyr * 4];
            ulonglong2 bp = *(const ulonglong2*)&Bs[cur][k][tx * 4];
            unsigned long long a0 = dup2(a.x), a1 = dup2(a.y),
                               a2 = dup2(a.z), a3 = dup2(a.w);
            fma2(acc2[0][0], a0, bp.x); fma2(acc2[0][1], a0, bp.y);
            fma2(acc2[1][0], a1, bp.x); fma2(acc2[1][1], a1, bp.y);
            fma2(acc2[2][0], a2, bp.x); fma2(acc2[2][1], a2, bp.y);
            fma2(acc2[3][0], a3, bp.x); fma2(acc2[3][1], a3, bp.y);
        }

        // store tile n+1 (its LDG completed ~a full tile ago)
        if (k0 + 16 < K) ST_TILE(cur ^ 1, av1, b01, b11);

        // rotate the register pipeline
        av1 = av2; b01 = b02; b11 = b12;

        __syncthreads();
        cur ^= 1;
    }
    #undef LD_TILE
    #undef ST_TILE

    // epilogue: float4 stores over n
    const int nb = n0 + tx * 4;
    float4 b4 = bias ? *(const float4*)&bias[nb] : make_float4(0.f, 0.f, 0.f, 0.f);
#pragma unroll
    for (int i = 0; i < 4; i++) {
        const int m = m0 + tyr * 4 + i;
        float4 v;
        unpack2(acc2[i][0], v.x, v.y);
        unpack2(acc2[i][1], v.z, v.w);
        v.x += b4.x; v.y += b4.y; v.z += b4.z; v.w += b4.w;
        if (Add) {
            float4 a4 = *(const float4*)&Add[(long)m * ldc + nb];
            v.x += a4.x; v.y += a4.y; v.z += a4.z; v.w += a4.w;
        }
        if (epi == 1) {
            v.x = fast_ex2(v.x * TWO_LOG2E); v.y = fast_ex2(v.y * TWO_LOG2E);
            v.z = fast_ex2(v.z * TWO_LOG2E); v.w = fast_ex2(v.w * TWO_LOG2E);
        } else if (epi == 2) {
            v.x = fast_tanh(v.x); v.y = fast_tanh(v.y);
            v.z = fast_tanh(v.z); v.w = fast_tanh(v.w);
        }
        *(float4*)&C[(long)m * ldc + nb] = v;
    }
}

// ---------------- fused input projections: Ec, Eq, qpart (576 CTAs) --------
__global__ __launch_bounds__(128)
void proj_fused_kernel(const float* __restrict__ context,
                       const float* __restrict__ query,
                       const float* __restrict__ wc_w, const float* __restrict__ wc_b,
                       const float* __restrict__ wq_w, const float* __restrict__ wq_b,
                       const float* __restrict__ lo_w, const float* __restrict__ lo_b,
                       float* __restrict__ Ec, float* __restrict__ Eq,
                       float* __restrict__ qpart)
{
    const int i = blockIdx.x;
    if (i < 256) {               // Ec: 128 m-tiles x 2 n-tiles
        const int m0 = (i >> 1) * 32, n0 = (i & 1) * 64;
        gemm32<true>(context, CDIM, wc_w, CDIM, wc_b, nullptr, Ec, HH,
                     CDIM, m0, n0, 1);
    } else if (i < 320) {        // Eq: 32 x 2
        const int j = i - 256;
        const int m0 = (j >> 1) * 32, n0 = (j & 1) * 64;
        gemm32<true>(query, QDIM, wq_w, QDIM, wq_b, nullptr, Eq, HH,
                     QDIM, m0, n0, 1);
    } else {                     // qpart: 32 x 8
        const int j = i - 320;
        const int m0 = (j >> 3) * 32, n0 = (j & 7) * 64;
        gemm32<true>(query, QDIM, lo_w + CDIM, QDIM + CDIM, lo_b, nullptr,
                     qpart, QDIM, QDIM, m0, n0, 0);
    }
}

// ---------------- wc = attn @ context (256 CTAs) ---------------------------
__global__ __launch_bounds__(128)
void gemm_nn_kernel(const float* __restrict__ attn,
                    const float* __restrict__ context,
                    float* __restrict__ wc)
{
    const int b = blockIdx.z;
    gemm32<false>(attn + (long)b * QQ * CCN, CCN,
                  context + (long)b * CCN * CDIM, CDIM,
                  nullptr, nullptr,
                  wc + (long)b * QQ * CDIM, CDIM,
                  CCN, blockIdx.y * 32, blockIdx.x * 64, 0);
}

// ---------------- out = tanh(wc @ lo_w[:,:512].T + qpart) (256 CTAs) -------
__global__ __launch_bounds__(128)
void gemm_out_kernel(const float* __restrict__ wc,
                     const float* __restrict__ lo_w,
                     const float* __restrict__ qpart,
                     float* __restrict__ out)
{
    gemm32<true>(wc, CDIM, lo_w, QDIM + CDIM, nullptr, qpart,
                 out, QDIM, CDIM, blockIdx.y * 32, blockIdx.x * 64, 2);
}

// ---------------- emission + masked softmax (unchanged) ----------------
#define QT 4
#define CH 32
#define NCHUNK (CCN / CH)
#define ECPAD 132

__global__ __launch_bounds__(128)
void emission_softmax2(const float* __restrict__ Ec,
                       const float* __restrict__ Eq,
                       const int* __restrict__ mask,
                       const float* __restrict__ we_w,
                       const float* __restrict__ we_b,
                       float* __restrict__ attn)
{
    __shared__ float ecs[CH][ECPAD];
    __shared__ float eqs[QT][HH];
    __shared__ float wes[HH];
    __shared__ int ms[CH];

    const int b  = blockIdx.y;
    const int q0 = blockIdx.x * QT;
    const int tid = threadIdx.x;
    const int lane = tid & 31;
    const int q = tid >> 5;

    if (tid < HH) wes[tid] = we_w[tid];
    {
        const float4* src = (const float4*)&Eq[(long)(b * QQ + q0) * HH];
        float4* dst = (float4*)&eqs[0][0];
        for (int i = tid; i < QT * HH / 4; i += 128) dst[i] = src[i];
    }
    __syncthreads();

    float W = 0.f;
#pragma unroll
    for (int h = 0; h < HH; h += 4) {
        float4 w4 = *(const float4*)&wes[h];
        W += (w4.x + w4.y) + (w4.z + w4.w);
    }
    const float eb = we_b[0];

    float es_l[NCHUNK];

    for (int ch = 0; ch < NCHUNK; ch++) {
        __syncthreads();
        {
            const float4* src = (const float4*)&Ec[((long)b * CCN + ch * CH) * HH];
            for (int i = tid; i < CH * HH / 4; i += 128) {
                int r  = i >> 5;
                int c4 = (i & 31) * 4;
                *(float4*)&ecs[r][c4] = src[i];
            }
            if (tid < CH) ms[tid] = mask[b * CCN + ch * CH + tid];
        }
        __syncthreads();

        float s0 = 0.f, s1 = 0.f;
#pragma unroll
        for (int h = 0; h < HH; h += 8) {
            float4 e0 = *(const float4*)&ecs[lane][h];
            float4 g0 = *(const float4*)&eqs[q][h];
            float4 w0 = *(const float4*)&wes[h];
            float4 e1 = *(const float4*)&ecs[lane][h + 4];
            float4 g1 = *(const float4*)&eqs[q][h + 4];
            float4 w1 = *(const float4*)&wes[h + 4];
            s0 += w0.x * fast_rcp(fmaf(e0.x, g0.x, 1.f));
            s1 += w0.y * fast_rcp(fmaf(e0.y, g0.y, 1.f));
            s0 += w0.z * fast_rcp(fmaf(e0.z, g0.z, 1.f));
            s1 += w0.w * fast_rcp(fmaf(e0.w, g0.w, 1.f));
            s0 += w1.x * fast_rcp(fmaf(e1.x, g1.x, 1.f));
            s1 += w1.y * fast_rcp(fmaf(e1.y, g1.y, 1.f));
            s0 += w1.z * fast_rcp(fmaf(e1.z, g1.z, 1.f));
            s1 += w1.w * fast_rcp(fmaf(e1.w, g1.w, 1.f));
        }
        float s = s0 + s1;
        es_l[ch] = ms[lane] ? (fmaf(-2.f, s, W) + eb) : -INFINITY;
    }

    float lm = -INFINITY;
#pragma unroll
    for (int ch = 0; ch < NCHUNK; ch++) lm = fmaxf(lm, es_l[ch]);
#pragma unroll
    for (int off = 16; off >= 1; off >>= 1)
        lm = fmaxf(lm, __shfl_xor_sync(0xffffffffu, lm, off));
    const bool ok = (lm > -3.0e38f);

    float ls = 0.f;
#pragma unroll
    for (int ch = 0; ch < NCHUNK; ch++) {
        float e = ok ? __expf(es_l[ch] - lm) : 0.f;
        es_l[ch] = e;
        ls += e;
    }
#pragma unroll
    for (int off = 16; off >= 1; off >>= 1)
        ls += __shfl_xor_sync(0xffffffffu, ls, off);
    const float inv = (ls > 0.f) ? 1.f / ls : 0.f;

    float* arow = attn + (long)(b * QQ + q0 + q) * CCN;
#pragma unroll
    for (int ch = 0; ch < NCHUNK; ch++) arow[ch * CH + lane] = es_l[ch] * inv;
}

// ---------------- launcher ----------------
extern "C" void kernel_launch(void* const* d_in, const int* in_sizes, int n_in,
                              void* d_out, int out_size)
{
    const float* query   = (const float*)d_in[0];
    const float* context = (const float*)d_in[1];
    const int*   mask    = (const int*)d_in[2];
    const float* wq_w = (const float*)d_in[3];
    const float* wq_b = (const float*)d_in[4];
    const float* wc_w = (const float*)d_in[5];
    const float* wc_b = (const float*)d_in[6];
    const float* we_w = (const float*)d_in[7];
    const float* we_b = (const float*)d_in[8];
    const float* lo_w = (const float*)d_in[9];
    const float* lo_b = (const float*)d_in[10];

    float *Ec, *Eq, *qpart, *wc, *attn_s;
    cudaGetSymbolAddress((void**)&Ec, g_Ec);
    cudaGetSymbolAddress((void**)&Eq, g_Eq);
    cudaGetSymbolAddress((void**)&qpart, g_qpart);
    cudaGetSymbolAddress((void**)&wc, g_wc);
    cudaGetSymbolAddress((void**)&attn_s, g_attn_scratch);

    const int nOut  = BB * QQ * QDIM;
    const int nAttn = BB * QQ * CCN;
    float* outPtr  = nullptr;
    float* attnPtr = nullptr;
    if (out_size >= nOut + nAttn) {
        outPtr  = (float*)d_out;
        attnPtr = (float*)d_out + nOut;
    } else if (out_size == nAttn) {
        attnPtr = (float*)d_out;
    } else {
        outPtr = (float*)d_out;
    }
    if (!attnPtr) attnPtr = attn_s;

    // 1) all input-only projections in one launch: Ec, Eq, qpart (576 CTAs)
    proj_fused_kernel<<<576, 128>>>(context, query, wc_w, wc_b, wq_w, wq_b,
                                    lo_w, lo_b, Ec, Eq, qpart);

    // 2) emission + softmax -> attn (256 CTAs)
    emission_softmax2<<<dim3(QQ / QT, BB), 128>>>(Ec, Eq, mask, we_w, we_b, attnPtr);

    if (outPtr) {
        // 3) wc = attn @ context (256 CTAs)
        gemm_nn_kernel<<<dim3(CDIM / 64, QQ / 32, BB), 128>>>(attnPtr, context, wc);

        // 4) out = tanh(wc @ lo_w[:,:512].T + qpart) (256 CTAs)
        gemm_out_kernel<<<dim3(QDIM / 64, BB * QQ / 32), 128>>>(wc, lo_w, qpart, outPtr);
    }
}